// round 1
// baseline (speedup 1.0000x reference)
#include <cuda_runtime.h>
#include <math.h>

#define N_NODES 50000
#define N_EDGES 800000
#define TE 128
#define LDA 104   // feat tile leading dim (>=96, mult of 4)
#define LDV 68    // v tile leading dim   (>=64, mult of 4)

// -------- scratch (static device globals; no allocation) --------
__device__ float g_diff[(size_t)N_EDGES * 12];
__device__ float g_radial[(size_t)N_EDGES * 16];
__device__ float g_v[(size_t)N_EDGES * 64];
__device__ float g_sumsq[16];
__device__ float g_inv[16];
__device__ float g_segsum[N_NODES];

// -------- K0: init outputs and accumulators --------
__global__ void k_init(const float* __restrict__ h, const float* __restrict__ coord,
                       float* __restrict__ out)
{
    int i = blockIdx.x * 256 + threadIdx.x;
    if (i < 3200000) out[i] = h[i];                       // h_out = h
    else if (i < 3800000) out[i] = coord[i - 3200000];    // coord_out = coord
    else if (i < 3850000) g_segsum[i - 3800000] = 0.f;
    else if (i < 3850016) g_sumsq[i - 3850000] = 0.f;
}

// -------- K1: coord_diff, raw radial, global sum of squares --------
__global__ __launch_bounds__(256) void k_radial(const float* __restrict__ coord,
                                                const int* __restrict__ row,
                                                const int* __restrict__ col)
{
    int e = blockIdx.x * 256 + threadIdx.x;
    float rad[16];
#pragma unroll
    for (int k = 0; k < 16; k++) rad[k] = 0.f;

    if (e < N_EDGES) {
        int r = row[e], c = col[e];
        const float4* pr = (const float4*)(coord + (size_t)r * 12);
        const float4* pc = (const float4*)(coord + (size_t)c * 12);
        float d[12];
#pragma unroll
        for (int q = 0; q < 3; q++) {
            float4 a = pr[q], b = pc[q];
            d[q*4+0] = a.x - b.x; d[q*4+1] = a.y - b.y;
            d[q*4+2] = a.z - b.z; d[q*4+3] = a.w - b.w;
        }
        float4* pd = (float4*)(g_diff + (size_t)e * 12);
        pd[0] = make_float4(d[0], d[1], d[2], d[3]);
        pd[1] = make_float4(d[4], d[5], d[6], d[7]);
        pd[2] = make_float4(d[8], d[9], d[10], d[11]);
#pragma unroll
        for (int ci = 0; ci < 4; ci++)
#pragma unroll
            for (int fi = 0; fi < 4; fi++)
                rad[ci*4+fi] = d[ci*3]*d[fi*3] + d[ci*3+1]*d[fi*3+1] + d[ci*3+2]*d[fi*3+2];
        float4* prad = (float4*)(g_radial + (size_t)e * 16);
        prad[0] = make_float4(rad[0],  rad[1],  rad[2],  rad[3]);
        prad[1] = make_float4(rad[4],  rad[5],  rad[6],  rad[7]);
        prad[2] = make_float4(rad[8],  rad[9],  rad[10], rad[11]);
        prad[3] = make_float4(rad[12], rad[13], rad[14], rad[15]);
    }

    // block-level reduce of per-edge rad^2 -> 16 global atomics per block
    float sq[16];
#pragma unroll
    for (int k = 0; k < 16; k++) sq[k] = rad[k] * rad[k];
#pragma unroll
    for (int off = 16; off > 0; off >>= 1)
#pragma unroll
        for (int k = 0; k < 16; k++)
            sq[k] += __shfl_down_sync(0xffffffffu, sq[k], off);

    __shared__ float red[16];
    if (threadIdx.x < 16) red[threadIdx.x] = 0.f;
    __syncthreads();
    if ((threadIdx.x & 31) == 0) {
#pragma unroll
        for (int k = 0; k < 16; k++) atomicAdd(&red[k], sq[k]);
    }
    __syncthreads();
    if (threadIdx.x < 16) atomicAdd(&g_sumsq[threadIdx.x], red[threadIdx.x]);
}

// -------- K2: inverse norm (16 values) --------
__global__ void k_norm()
{
    int t = threadIdx.x;
    if (t < 16) g_inv[t] = 1.f / fmaxf(sqrtf(g_sumsq[t]), 1e-12f);
}

// -------- K3: q GEMM + kv GEMM + alpha + exp + segment sum --------
// 128-edge tile, 256 threads; thread (eg,og): eg=tid>>4 edges eg*8..+7,
// q cols og*4..+3, kv cols og*8..+7 (so k cols og*4..+3 -> alpha partial is local)
__global__ __launch_bounds__(256, 2) void k_qkv(
    const float* __restrict__ h, const float* __restrict__ edge_attr,
    const int* __restrict__ row, const int* __restrict__ col,
    const float* __restrict__ Wq, const float* __restrict__ bq,
    const float* __restrict__ Wkv, const float* __restrict__ bkv,
    float* __restrict__ ex_out)
{
    extern __shared__ float sm3[];
    float* sW = sm3;              // 12288 floats (Wq then Wkv)
    float* sA = sm3 + 12288;      // TE*LDA = 13312 floats (hrow then feat)
    int* sRow = (int*)(sm3 + 25600);
    int* sCol = sRow + TE;

    const int tid = threadIdx.x;
    const int e0 = blockIdx.x * TE;

    if (tid < TE) sRow[tid] = row[e0 + tid];
    else if (tid < 2 * TE) sCol[tid - TE] = col[e0 + tid - TE];

    for (int i = tid; i < 1024; i += 256)
        ((float4*)sW)[i] = ((const float4*)Wq)[i];
    __syncthreads();

    // gather h[row] rows into sA
    for (int idx = tid; idx < TE * 16; idx += 256) {
        int e = idx >> 4, c4 = idx & 15;
        *(float4*)(sA + e * LDA + c4 * 4) =
            *(const float4*)(h + (size_t)sRow[e] * 64 + c4 * 4);
    }
    __syncthreads();

    const int eg = tid >> 4, og = tid & 15;
    const float* aBase = sA + eg * 8 * LDA;

    // ---- q = h[row] @ Wq + bq ----
    float accq[8][4];
    {
        float4 b = *(const float4*)(bq + og * 4);
#pragma unroll
        for (int i = 0; i < 8; i++) { accq[i][0]=b.x; accq[i][1]=b.y; accq[i][2]=b.z; accq[i][3]=b.w; }
    }
#pragma unroll 4
    for (int k = 0; k < 64; k++) {
        float4 w = *(const float4*)(sW + k * 64 + og * 4);
#pragma unroll
        for (int i = 0; i < 8; i++) {
            float a = aBase[i * LDA + k];
            accq[i][0] += a * w.x; accq[i][1] += a * w.y;
            accq[i][2] += a * w.z; accq[i][3] += a * w.w;
        }
    }
    __syncthreads();

    // ---- stage Wkv and feat = [radial/norm (16) | h[col] (64) | edge_attr (16)] ----
    for (int i = tid; i < 3072; i += 256)
        ((float4*)sW)[i] = ((const float4*)Wkv)[i];
    for (int idx = tid; idx < TE * 24; idx += 256) {
        int e = idx / 24, c4 = idx % 24;
        float4 v;
        if (c4 < 4) {
            v = *(const float4*)(g_radial + (size_t)(e0 + e) * 16 + c4 * 4);
            float4 inv = *(const float4*)(g_inv + c4 * 4);
            v.x *= inv.x; v.y *= inv.y; v.z *= inv.z; v.w *= inv.w;
        } else if (c4 < 20) {
            v = *(const float4*)(h + (size_t)sCol[e] * 64 + (c4 - 4) * 4);
        } else {
            v = *(const float4*)(edge_attr + (size_t)(e0 + e) * 16 + (c4 - 20) * 4);
        }
        *(float4*)(sA + e * LDA + c4 * 4) = v;
    }
    __syncthreads();

    // ---- kv = feat @ Wkv + bkv ----
    float acc[8][8];
    {
        float4 b0 = *(const float4*)(bkv + og * 8);
        float4 b1v = *(const float4*)(bkv + og * 8 + 4);
#pragma unroll
        for (int i = 0; i < 8; i++) {
            acc[i][0]=b0.x; acc[i][1]=b0.y; acc[i][2]=b0.z; acc[i][3]=b0.w;
            acc[i][4]=b1v.x; acc[i][5]=b1v.y; acc[i][6]=b1v.z; acc[i][7]=b1v.w;
        }
    }
#pragma unroll 4
    for (int k = 0; k < 96; k++) {
        float4 w0 = *(const float4*)(sW + k * 128 + og * 8);
        float4 w1 = *(const float4*)(sW + k * 128 + og * 8 + 4);
#pragma unroll
        for (int i = 0; i < 8; i++) {
            float a = aBase[i * LDA + k];
            acc[i][0] += a * w0.x; acc[i][1] += a * w0.y;
            acc[i][2] += a * w0.z; acc[i][3] += a * w0.w;
            acc[i][4] += a * w1.x; acc[i][5] += a * w1.y;
            acc[i][6] += a * w1.z; acc[i][7] += a * w1.w;
        }
    }

    // ---- store v (odd kv cols), alpha partial from matching q/k cols ----
    float p[8];
#pragma unroll
    for (int i = 0; i < 8; i++) {
        int e = e0 + eg * 8 + i;
        float4 vv = make_float4(acc[i][1], acc[i][3], acc[i][5], acc[i][7]);
        *(float4*)(g_v + (size_t)e * 64 + og * 4) = vv;
        p[i] = accq[i][0]*acc[i][0] + accq[i][1]*acc[i][2]
             + accq[i][2]*acc[i][4] + accq[i][3]*acc[i][6];
    }
#pragma unroll
    for (int off = 8; off > 0; off >>= 1)
#pragma unroll
        for (int i = 0; i < 8; i++)
            p[i] += __shfl_down_sync(0xffffffffu, p[i], off, 16);

    if (og == 0) {
#pragma unroll
        for (int i = 0; i < 8; i++) {
            int el = eg * 8 + i;
            float ex = expf(p[i]);         // softmax shift-invariant; |alpha| <~ 15
            ex_out[e0 + el] = ex;
            atomicAdd(&g_segsum[sRow[el]], ex);
        }
    }
}

// -------- K4: att normalize, MLP silu(v@W1+b1)@W2, scatter h_out & coord_out --------
__global__ __launch_bounds__(256) void k_mlp(
    const float* __restrict__ W1, const float* __restrict__ b1,
    const float* __restrict__ W2, const int* __restrict__ row,
    float* __restrict__ att_io, float* __restrict__ h_out, float* __restrict__ coord_out)
{
    extern __shared__ float sm4[];
    float* sW1 = sm4;               // 4096
    float* sW2 = sm4 + 4096;        // 256
    float* sB1 = sm4 + 4352;        // 64
    float* sV  = sm4 + 4416;        // TE*LDV = 8704
    float* sAtt= sm4 + 13120;       // 128
    float* sU  = sm4 + 13248;       // 512
    int*  sRow = (int*)(sm4 + 13760); // 128 ints

    const int tid = threadIdx.x;
    const int e0 = blockIdx.x * TE;

    if (tid < TE) sRow[tid] = row[e0 + tid];
    for (int i = tid; i < 1024; i += 256)
        ((float4*)sW1)[i] = ((const float4*)W1)[i];
    if (tid < 64) ((float4*)sW2)[tid] = ((const float4*)W2)[tid];
    else if (tid < 80) ((float4*)sB1)[tid - 64] = ((const float4*)b1)[tid - 64];
    for (int idx = tid; idx < TE * 16; idx += 256) {
        int e = idx >> 4, c4 = idx & 15;
        *(float4*)(sV + e * LDV + c4 * 4) =
            *(const float4*)(g_v + (size_t)(e0 + e) * 64 + c4 * 4);
    }
    __syncthreads();

    if (tid < TE) {
        float a = att_io[e0 + tid] / g_segsum[sRow[tid]];
        sAtt[tid] = a;
        att_io[e0 + tid] = a;   // final att output
    }

    const int eg = tid >> 4, og = tid & 15;
    const float* vBase = sV + eg * 8 * LDV;

    float acct[8][4];
    {
        float4 b = *(const float4*)(sB1 + og * 4);
#pragma unroll
        for (int i = 0; i < 8; i++) { acct[i][0]=b.x; acct[i][1]=b.y; acct[i][2]=b.z; acct[i][3]=b.w; }
    }
#pragma unroll 4
    for (int k = 0; k < 64; k++) {
        float4 w = *(const float4*)(sW1 + k * 64 + og * 4);
#pragma unroll
        for (int i = 0; i < 8; i++) {
            float a = vBase[i * LDV + k];
            acct[i][0] += a * w.x; acct[i][1] += a * w.y;
            acct[i][2] += a * w.z; acct[i][3] += a * w.w;
        }
    }
    // silu
#pragma unroll
    for (int i = 0; i < 8; i++)
#pragma unroll
        for (int c = 0; c < 4; c++) {
            float x = acct[i][c];
            acct[i][c] = x / (1.f + expf(-x));
        }

    // u = t @ W2 : partial over this thread's 4 cols, reduce across og
    float pu[8][4];
#pragma unroll
    for (int i = 0; i < 8; i++) { pu[i][0]=0.f; pu[i][1]=0.f; pu[i][2]=0.f; pu[i][3]=0.f; }
#pragma unroll
    for (int c = 0; c < 4; c++) {
        float4 w2 = *(const float4*)(sW2 + (og * 4 + c) * 4);
#pragma unroll
        for (int i = 0; i < 8; i++) {
            float t = acct[i][c];
            pu[i][0] += t * w2.x; pu[i][1] += t * w2.y;
            pu[i][2] += t * w2.z; pu[i][3] += t * w2.w;
        }
    }
#pragma unroll
    for (int off = 8; off > 0; off >>= 1)
#pragma unroll
        for (int i = 0; i < 8; i++)
#pragma unroll
            for (int c2 = 0; c2 < 4; c2++)
                pu[i][c2] += __shfl_down_sync(0xffffffffu, pu[i][c2], off, 16);
    if (og == 0) {
#pragma unroll
        for (int i = 0; i < 8; i++)
            *(float4*)(sU + (eg * 8 + i) * 4) = make_float4(pu[i][0], pu[i][1], pu[i][2], pu[i][3]);
    }
    __syncthreads();

    // scatter h_out += att * v  (coalesced consecutive addresses per warp)
    for (int idx = tid; idx < TE * 16; idx += 256) {
        int e = idx >> 4, c4 = idx & 15;
        float at = sAtt[e];
        float4 v4 = *(const float4*)(sV + e * LDV + c4 * 4);
        float* dst = h_out + (size_t)sRow[e] * 64 + c4 * 4;
        atomicAdd(dst + 0, at * v4.x);
        atomicAdd(dst + 1, at * v4.y);
        atomicAdd(dst + 2, at * v4.z);
        atomicAdd(dst + 3, at * v4.w);
    }
    // scatter coord_out += diff * (att*u)
    for (int idx = tid; idx < TE * 4; idx += 256) {
        int e = idx >> 2, c = idx & 3;
        float cv = sAtt[e] * sU[e * 4 + c];
        const float* dp = g_diff + (size_t)(e0 + e) * 12 + c * 3;
        float* dst = coord_out + (size_t)sRow[e] * 12 + c * 3;
        atomicAdd(dst + 0, dp[0] * cv);
        atomicAdd(dst + 1, dp[1] * cv);
        atomicAdd(dst + 2, dp[2] * cv);
    }
}

// -------- launch --------
extern "C" void kernel_launch(void* const* d_in, const int* in_sizes, int n_in,
                              void* d_out, int out_size)
{
    const float *h=0, *coord=0, *edge_attr=0, *Wq=0, *bq=0, *Wkv=0, *bkv=0, *W1=0, *b1=0, *W2=0;
    const int *row=0, *col=0;
    for (int i = 0; i < n_in; i++) {
        int s = in_sizes[i]; const void* p = d_in[i];
        switch (s) {
            case 3200000:  h = (const float*)p; break;
            case 600000:   coord = (const float*)p; break;
            case 800000:   if (!row) row = (const int*)p; else col = (const int*)p; break;
            case 12800000: edge_attr = (const float*)p; break;
            case 4096:     if (!Wq) Wq = (const float*)p; else W1 = (const float*)p; break;
            case 64:       if (!bq) bq = (const float*)p; else b1 = (const float*)p; break;
            case 12288:    Wkv = (const float*)p; break;
            case 128:      bkv = (const float*)p; break;
            case 256:      W2 = (const float*)p; break;
            default: break;
        }
    }
    float* out = (float*)d_out;
    float* h_out = out;
    float* coord_out = out + 3200000;
    float* att = out + 3800000;

    cudaFuncSetAttribute(k_qkv, cudaFuncAttributeMaxDynamicSharedMemorySize, 103424);
    cudaFuncSetAttribute(k_mlp, cudaFuncAttributeMaxDynamicSharedMemorySize, 55552);

    k_init<<<(3850016 + 255) / 256, 256>>>(h, coord, out);
    k_radial<<<N_EDGES / 256, 256>>>(coord, row, col);
    k_norm<<<1, 16>>>();
    k_qkv<<<N_EDGES / TE, 256, 103424>>>(h, edge_attr, row, col, Wq, bq, Wkv, bkv, att);
    k_mlp<<<N_EDGES / TE, 256, 55552>>>(W1, b1, W2, row, att, h_out, coord_out);
}

// round 2
// speedup vs baseline: 1.1586x; 1.1586x over previous
#include <cuda_runtime.h>
#include <math.h>

#define N_NODES 50000
#define N_EDGES 800000
#define TE 128
#define LDA 104   // feat tile leading dim (>=96, mult of 4)
#define LDV 68    // v tile leading dim   (>=64, mult of 4)

// -------- scratch (static device globals; no allocation) --------
__device__ float g_diff[(size_t)N_EDGES * 12];
__device__ float g_radial[(size_t)N_EDGES * 16];
__device__ float g_hnum[(size_t)N_NODES * 64];
__device__ float g_cnum[(size_t)N_NODES * 12];
__device__ float g_sumsq[16];
__device__ float g_inv[16];
__device__ float g_segsum[N_NODES];

__device__ __forceinline__ void red_add_v4(float* p, float a, float b, float c, float d)
{
    asm volatile("red.global.add.v4.f32 [%0], {%1, %2, %3, %4};"
                 :: "l"(p), "f"(a), "f"(b), "f"(c), "f"(d) : "memory");
}

// -------- K0: zero accumulators --------
__global__ void k_init()
{
    int i = blockIdx.x * 256 + threadIdx.x;
    if (i < 3200000) g_hnum[i] = 0.f;
    else if (i < 3800000) g_cnum[i - 3200000] = 0.f;
    else if (i < 3850000) g_segsum[i - 3800000] = 0.f;
    else if (i < 3850016) g_sumsq[i - 3850000] = 0.f;
}

// -------- K1: coord_diff, raw radial, global sum of squares --------
__global__ __launch_bounds__(256) void k_radial(const float* __restrict__ coord,
                                                const int* __restrict__ row,
                                                const int* __restrict__ col)
{
    int e = blockIdx.x * 256 + threadIdx.x;
    float rad[16];
#pragma unroll
    for (int k = 0; k < 16; k++) rad[k] = 0.f;

    if (e < N_EDGES) {
        int r = row[e], c = col[e];
        const float4* pr = (const float4*)(coord + (size_t)r * 12);
        const float4* pc = (const float4*)(coord + (size_t)c * 12);
        float d[12];
#pragma unroll
        for (int q = 0; q < 3; q++) {
            float4 a = pr[q], b = pc[q];
            d[q*4+0] = a.x - b.x; d[q*4+1] = a.y - b.y;
            d[q*4+2] = a.z - b.z; d[q*4+3] = a.w - b.w;
        }
        float4* pd = (float4*)(g_diff + (size_t)e * 12);
        pd[0] = make_float4(d[0], d[1], d[2], d[3]);
        pd[1] = make_float4(d[4], d[5], d[6], d[7]);
        pd[2] = make_float4(d[8], d[9], d[10], d[11]);
#pragma unroll
        for (int ci = 0; ci < 4; ci++)
#pragma unroll
            for (int fi = 0; fi < 4; fi++)
                rad[ci*4+fi] = d[ci*3]*d[fi*3] + d[ci*3+1]*d[fi*3+1] + d[ci*3+2]*d[fi*3+2];
        float4* prad = (float4*)(g_radial + (size_t)e * 16);
        prad[0] = make_float4(rad[0],  rad[1],  rad[2],  rad[3]);
        prad[1] = make_float4(rad[4],  rad[5],  rad[6],  rad[7]);
        prad[2] = make_float4(rad[8],  rad[9],  rad[10], rad[11]);
        prad[3] = make_float4(rad[12], rad[13], rad[14], rad[15]);
    }

    float sq[16];
#pragma unroll
    for (int k = 0; k < 16; k++) sq[k] = rad[k] * rad[k];
#pragma unroll
    for (int off = 16; off > 0; off >>= 1)
#pragma unroll
        for (int k = 0; k < 16; k++)
            sq[k] += __shfl_down_sync(0xffffffffu, sq[k], off);

    __shared__ float red[16];
    if (threadIdx.x < 16) red[threadIdx.x] = 0.f;
    __syncthreads();
    if ((threadIdx.x & 31) == 0) {
#pragma unroll
        for (int k = 0; k < 16; k++) atomicAdd(&red[k], sq[k]);
    }
    __syncthreads();
    if (threadIdx.x < 16) atomicAdd(&g_sumsq[threadIdx.x], red[threadIdx.x]);
}

// -------- K2: inverse norm (16 values) --------
__global__ void k_norm()
{
    int t = threadIdx.x;
    if (t < 16) g_inv[t] = 1.f / fmaxf(sqrtf(g_sumsq[t]), 1e-12f);
}

// -------- K3: fully fused edge kernel --------
// q GEMM + kv GEMM + alpha/exp + MLP(silu(v@W1+b1)@W2) + scatter of
// UNNORMALIZED numerators (ex*v -> g_hnum, ex*u*diff -> g_cnum).
// Thread (eg,og): eg=tid>>4 owns edges eg*8..+7; og=tid&15 owns
// q cols og*4..+3 and kv cols og*8..+7 (k cols og*4..+3 match q -> local alpha).
__global__ __launch_bounds__(256, 2) void k_fused(
    const float* __restrict__ h, const float* __restrict__ edge_attr,
    const int* __restrict__ row, const int* __restrict__ col,
    const float* __restrict__ Wq, const float* __restrict__ bq,
    const float* __restrict__ Wkv, const float* __restrict__ bkv,
    const float* __restrict__ W1, const float* __restrict__ b1,
    const float* __restrict__ W2,
    float* __restrict__ ex_out)
{
    extern __shared__ float sm[];
    float* sW  = sm;                 // 12288 (Wq | Wkv | W1+W2+b1)
    float* sA  = sm + 12288;         // 13312 = TE*LDA (h[row] | feat | v tile)
    float* sEx = sm + 25600;         // 128
    float* sU  = sm + 25728;         // 512
    int* sRow  = (int*)(sm + 26240); // 128
    int* sCol  = sRow + TE;          // 128

    const int tid = threadIdx.x;
    const int e0 = blockIdx.x * TE;

    if (tid < TE) sRow[tid] = row[e0 + tid];
    else sCol[tid - TE] = col[e0 + tid - TE];

    for (int i = tid; i < 1024; i += 256)
        ((float4*)sW)[i] = ((const float4*)Wq)[i];
    __syncthreads();

    // gather h[row] rows into sA
    for (int idx = tid; idx < TE * 16; idx += 256) {
        int e = idx >> 4, c4 = idx & 15;
        *(float4*)(sA + e * LDA + c4 * 4) =
            *(const float4*)(h + (size_t)sRow[e] * 64 + c4 * 4);
    }
    __syncthreads();

    const int eg = tid >> 4, og = tid & 15;
    const float* aBase = sA + eg * 8 * LDA;

    // ---- q = h[row] @ Wq + bq (vectorized A reads) ----
    float accq[8][4];
    {
        float4 b = *(const float4*)(bq + og * 4);
#pragma unroll
        for (int i = 0; i < 8; i++) { accq[i][0]=b.x; accq[i][1]=b.y; accq[i][2]=b.z; accq[i][3]=b.w; }
    }
#pragma unroll 2
    for (int k4 = 0; k4 < 16; k4++) {
        float4 a4[8];
#pragma unroll
        for (int i = 0; i < 8; i++)
            a4[i] = *(const float4*)(aBase + i * LDA + k4 * 4);
#pragma unroll
        for (int kk = 0; kk < 4; kk++) {
            float4 w = *(const float4*)(sW + (k4 * 4 + kk) * 64 + og * 4);
#pragma unroll
            for (int i = 0; i < 8; i++) {
                float a = ((const float*)&a4[i])[kk];
                accq[i][0] += a * w.x; accq[i][1] += a * w.y;
                accq[i][2] += a * w.z; accq[i][3] += a * w.w;
            }
        }
    }
    __syncthreads();

    // ---- stage Wkv; feat = [radial/norm (16) | h[col] (64) | edge_attr (16)] ----
    for (int i = tid; i < 3072; i += 256)
        ((float4*)sW)[i] = ((const float4*)Wkv)[i];
    for (int idx = tid; idx < TE * 24; idx += 256) {
        int e = idx / 24, c4 = idx % 24;
        float4 v;
        if (c4 < 4) {
            v = *(const float4*)(g_radial + (size_t)(e0 + e) * 16 + c4 * 4);
            float4 inv = *(const float4*)(g_inv + c4 * 4);
            v.x *= inv.x; v.y *= inv.y; v.z *= inv.z; v.w *= inv.w;
        } else if (c4 < 20) {
            v = *(const float4*)(h + (size_t)sCol[e] * 64 + (c4 - 4) * 4);
        } else {
            v = *(const float4*)(edge_attr + (size_t)(e0 + e) * 16 + (c4 - 20) * 4);
        }
        *(float4*)(sA + e * LDA + c4 * 4) = v;
    }
    __syncthreads();

    // ---- kv = feat @ Wkv + bkv (vectorized A, 4-edge halves for regs) ----
    float acc[8][8];
    {
        float4 b0 = *(const float4*)(bkv + og * 8);
        float4 b1v = *(const float4*)(bkv + og * 8 + 4);
#pragma unroll
        for (int i = 0; i < 8; i++) {
            acc[i][0]=b0.x; acc[i][1]=b0.y; acc[i][2]=b0.z; acc[i][3]=b0.w;
            acc[i][4]=b1v.x; acc[i][5]=b1v.y; acc[i][6]=b1v.z; acc[i][7]=b1v.w;
        }
    }
#pragma unroll 2
    for (int k4 = 0; k4 < 24; k4++) {
#pragma unroll
        for (int half = 0; half < 2; half++) {
            float4 a4[4];
#pragma unroll
            for (int i = 0; i < 4; i++)
                a4[i] = *(const float4*)(aBase + (half * 4 + i) * LDA + k4 * 4);
#pragma unroll
            for (int kk = 0; kk < 4; kk++) {
                const float* wp = sW + (k4 * 4 + kk) * 128 + og * 8;
                float4 w0 = *(const float4*)wp;
                float4 w1 = *(const float4*)(wp + 4);
#pragma unroll
                for (int i = 0; i < 4; i++) {
                    float a = ((const float*)&a4[i])[kk];
                    int ii = half * 4 + i;
                    acc[ii][0] += a * w0.x; acc[ii][1] += a * w0.y;
                    acc[ii][2] += a * w0.z; acc[ii][3] += a * w0.w;
                    acc[ii][4] += a * w1.x; acc[ii][5] += a * w1.y;
                    acc[ii][6] += a * w1.z; acc[ii][7] += a * w1.w;
                }
            }
        }
    }

    // ---- alpha = q.k (even cols), shuffle-reduce over og ----
    float p[8];
#pragma unroll
    for (int i = 0; i < 8; i++)
        p[i] = accq[i][0]*acc[i][0] + accq[i][1]*acc[i][2]
             + accq[i][2]*acc[i][4] + accq[i][3]*acc[i][6];
#pragma unroll
    for (int off = 8; off > 0; off >>= 1)
#pragma unroll
        for (int i = 0; i < 8; i++)
            p[i] += __shfl_down_sync(0xffffffffu, p[i], off, 16);

    if (og == 0) {
#pragma unroll
        for (int i = 0; i < 8; i++) {
            int el = eg * 8 + i;
            float ex = __expf(p[i]);     // softmax shift-invariant; |alpha| <~ 15
            sEx[el] = ex;
            ex_out[e0 + el] = ex;        // normalized in k_final
            atomicAdd(&g_segsum[sRow[el]], ex);
        }
    }
    __syncthreads();   // all done reading sA(feat)/sW(Wkv); sEx visible after next sync

    // ---- write v (odd kv cols) into sA as a TExLDV tile; stage W1/W2/b1 ----
#pragma unroll
    for (int i = 0; i < 8; i++)
        *(float4*)(sA + (eg * 8 + i) * LDV + og * 4) =
            make_float4(acc[i][1], acc[i][3], acc[i][5], acc[i][7]);

    for (int i = tid; i < 1024; i += 256)
        ((float4*)sW)[i] = ((const float4*)W1)[i];
    if (tid < 64) ((float4*)(sW + 4096))[tid] = ((const float4*)W2)[tid];
    else if (tid < 80) ((float4*)(sW + 4352))[tid - 64] = ((const float4*)b1)[tid - 64];
    __syncthreads();

    // ---- t = silu(v @ W1 + b1) ----
    const float* vBase = sA + eg * 8 * LDV;
    float acct[8][4];
    {
        float4 b = *(const float4*)(sW + 4352 + og * 4);
#pragma unroll
        for (int i = 0; i < 8; i++) { acct[i][0]=b.x; acct[i][1]=b.y; acct[i][2]=b.z; acct[i][3]=b.w; }
    }
#pragma unroll 2
    for (int k4 = 0; k4 < 16; k4++) {
        float4 a4[8];
#pragma unroll
        for (int i = 0; i < 8; i++)
            a4[i] = *(const float4*)(vBase + i * LDV + k4 * 4);
#pragma unroll
        for (int kk = 0; kk < 4; kk++) {
            float4 w = *(const float4*)(sW + (k4 * 4 + kk) * 64 + og * 4);
#pragma unroll
            for (int i = 0; i < 8; i++) {
                float a = ((const float*)&a4[i])[kk];
                acct[i][0] += a * w.x; acct[i][1] += a * w.y;
                acct[i][2] += a * w.z; acct[i][3] += a * w.w;
            }
        }
    }
#pragma unroll
    for (int i = 0; i < 8; i++)
#pragma unroll
        for (int c = 0; c < 4; c++) {
            float x = acct[i][c];
            acct[i][c] = x / (1.f + __expf(-x));
        }

    // ---- u = t @ W2 (partials over this thread's 4 cols, reduce across og) ----
    float pu[8][4];
#pragma unroll
    for (int i = 0; i < 8; i++) { pu[i][0]=0.f; pu[i][1]=0.f; pu[i][2]=0.f; pu[i][3]=0.f; }
#pragma unroll
    for (int c = 0; c < 4; c++) {
        float4 w2 = *(const float4*)(sW + 4096 + (og * 4 + c) * 4);
#pragma unroll
        for (int i = 0; i < 8; i++) {
            float t = acct[i][c];
            pu[i][0] += t * w2.x; pu[i][1] += t * w2.y;
            pu[i][2] += t * w2.z; pu[i][3] += t * w2.w;
        }
    }
#pragma unroll
    for (int off = 8; off > 0; off >>= 1)
#pragma unroll
        for (int i = 0; i < 8; i++)
#pragma unroll
            for (int c2 = 0; c2 < 4; c2++)
                pu[i][c2] += __shfl_down_sync(0xffffffffu, pu[i][c2], off, 16);
    if (og == 0) {
#pragma unroll
        for (int i = 0; i < 8; i++)
            *(float4*)(sU + (eg * 8 + i) * 4) = make_float4(pu[i][0], pu[i][1], pu[i][2], pu[i][3]);
    }
    __syncthreads();

    // ---- scatter UNNORMALIZED numerators (vector atomics, 16B aligned) ----
    for (int idx = tid; idx < TE * 16; idx += 256) {
        int e = idx >> 4, c4 = idx & 15;
        float ex = sEx[e];
        float4 v4 = *(const float4*)(sA + e * LDV + c4 * 4);
        red_add_v4(g_hnum + (size_t)sRow[e] * 64 + c4 * 4,
                   ex * v4.x, ex * v4.y, ex * v4.z, ex * v4.w);
    }
    for (int idx = tid; idx < TE * 3; idx += 256) {
        int e = idx / 3, pp = idx % 3;
        float ex = sEx[e];
        const float* dp = g_diff + (size_t)(e0 + e) * 12 + pp * 4;
        float vals[4];
#pragma unroll
        for (int j = 0; j < 4; j++) {
            int jj = pp * 4 + j;
            int ch = jj / 3;
            vals[j] = dp[j] * (ex * sU[e * 4 + ch]);
        }
        red_add_v4(g_cnum + (size_t)sRow[e] * 12 + pp * 4,
                   vals[0], vals[1], vals[2], vals[3]);
    }
}

// -------- K4: normalize everything into out --------
__global__ void k_final(const float* __restrict__ h, const float* __restrict__ coord,
                        const int* __restrict__ row, float* __restrict__ out)
{
    int i = blockIdx.x * 256 + threadIdx.x;
    if (i < 3200000) {
        out[i] = h[i] + g_hnum[i] / g_segsum[i >> 6];
    } else if (i < 3800000) {
        int j = i - 3200000;
        out[i] = coord[j] + g_cnum[j] / g_segsum[j / 12];
    } else if (i < 4600000) {
        int e = i - 3800000;
        out[i] = out[i] / g_segsum[row[e]];
    }
}

// -------- launch --------
extern "C" void kernel_launch(void* const* d_in, const int* in_sizes, int n_in,
                              void* d_out, int out_size)
{
    const float *h=0, *coord=0, *edge_attr=0, *Wq=0, *bq=0, *Wkv=0, *bkv=0, *W1=0, *b1=0, *W2=0;
    const int *row=0, *col=0;
    for (int i = 0; i < n_in; i++) {
        int s = in_sizes[i]; const void* p = d_in[i];
        switch (s) {
            case 3200000:  h = (const float*)p; break;
            case 600000:   coord = (const float*)p; break;
            case 800000:   if (!row) row = (const int*)p; else col = (const int*)p; break;
            case 12800000: edge_attr = (const float*)p; break;
            case 4096:     if (!Wq) Wq = (const float*)p; else W1 = (const float*)p; break;
            case 64:       if (!bq) bq = (const float*)p; else b1 = (const float*)p; break;
            case 12288:    Wkv = (const float*)p; break;
            case 128:      bkv = (const float*)p; break;
            case 256:      W2 = (const float*)p; break;
            default: break;
        }
    }
    float* out = (float*)d_out;
    float* att = out + 3800000;

    cudaFuncSetAttribute(k_fused, cudaFuncAttributeMaxDynamicSharedMemorySize, 106496);

    k_init<<<(3850016 + 255) / 256, 256>>>();
    k_radial<<<N_EDGES / 256, 256>>>(coord, row, col);
    k_norm<<<1, 16>>>();
    k_fused<<<N_EDGES / TE, 256, 106496>>>(h, edge_attr, row, col,
                                           Wq, bq, Wkv, bkv, W1, b1, W2, att);
    k_final<<<(4600000 + 255) / 256, 256>>>(h, coord, row, out);
}

// round 3
// speedup vs baseline: 2.1608x; 1.8650x over previous
#include <cuda_runtime.h>
#include <math.h>

#define N_NODES 50000
#define N_EDGES 800000
#define TE 128
#define LDF 36    // per-edge feat tile leading dim (32 data + pad)
#define LDV 68    // v tile leading dim (64 data + pad)
#define LDH 68    // node h tile leading dim

// -------- scratch (static device globals; no allocation) --------
__device__ float g_diff[(size_t)N_EDGES * 12];
__device__ float g_radial[(size_t)N_EDGES * 16];
__device__ float g_qn[(size_t)N_NODES * 64];
__device__ float g_hkv[(size_t)N_NODES * 128];
__device__ float g_hnum[(size_t)N_NODES * 64];
__device__ float g_cnum[(size_t)N_NODES * 12];
__device__ float g_sumsq[16];
__device__ float g_inv[16];
__device__ float g_segsum[N_NODES];

__device__ __forceinline__ void red_add_v4(float* p, float a, float b, float c, float d)
{
    asm volatile("red.global.add.v4.f32 [%0], {%1, %2, %3, %4};"
                 :: "l"(p), "f"(a), "f"(b), "f"(c), "f"(d) : "memory");
}

// -------- K0: zero accumulators --------
__global__ void k_init()
{
    int i = blockIdx.x * 256 + threadIdx.x;
    if (i < 3200000) g_hnum[i] = 0.f;
    else if (i < 3800000) g_cnum[i - 3200000] = 0.f;
    else if (i < 3850000) g_segsum[i - 3800000] = 0.f;
    else if (i < 3850016) g_sumsq[i - 3850000] = 0.f;
}

// -------- K1: coord_diff, raw radial, global sum of squares --------
__global__ __launch_bounds__(256) void k_radial(const float* __restrict__ coord,
                                                const int* __restrict__ row,
                                                const int* __restrict__ col)
{
    int e = blockIdx.x * 256 + threadIdx.x;
    float rad[16];
#pragma unroll
    for (int k = 0; k < 16; k++) rad[k] = 0.f;

    if (e < N_EDGES) {
        int r = row[e], c = col[e];
        const float4* pr = (const float4*)(coord + (size_t)r * 12);
        const float4* pc = (const float4*)(coord + (size_t)c * 12);
        float d[12];
#pragma unroll
        for (int q = 0; q < 3; q++) {
            float4 a = pr[q], b = pc[q];
            d[q*4+0] = a.x - b.x; d[q*4+1] = a.y - b.y;
            d[q*4+2] = a.z - b.z; d[q*4+3] = a.w - b.w;
        }
        float4* pd = (float4*)(g_diff + (size_t)e * 12);
        pd[0] = make_float4(d[0], d[1], d[2], d[3]);
        pd[1] = make_float4(d[4], d[5], d[6], d[7]);
        pd[2] = make_float4(d[8], d[9], d[10], d[11]);
#pragma unroll
        for (int ci = 0; ci < 4; ci++)
#pragma unroll
            for (int fi = 0; fi < 4; fi++)
                rad[ci*4+fi] = d[ci*3]*d[fi*3] + d[ci*3+1]*d[fi*3+1] + d[ci*3+2]*d[fi*3+2];
        float4* prad = (float4*)(g_radial + (size_t)e * 16);
        prad[0] = make_float4(rad[0],  rad[1],  rad[2],  rad[3]);
        prad[1] = make_float4(rad[4],  rad[5],  rad[6],  rad[7]);
        prad[2] = make_float4(rad[8],  rad[9],  rad[10], rad[11]);
        prad[3] = make_float4(rad[12], rad[13], rad[14], rad[15]);
    }

    float sq[16];
#pragma unroll
    for (int k = 0; k < 16; k++) sq[k] = rad[k] * rad[k];
#pragma unroll
    for (int off = 16; off > 0; off >>= 1)
#pragma unroll
        for (int k = 0; k < 16; k++)
            sq[k] += __shfl_down_sync(0xffffffffu, sq[k], off);

    __shared__ float red[16];
    if (threadIdx.x < 16) red[threadIdx.x] = 0.f;
    __syncthreads();
    if ((threadIdx.x & 31) == 0) {
#pragma unroll
        for (int k = 0; k < 16; k++) atomicAdd(&red[k], sq[k]);
    }
    __syncthreads();
    if (threadIdx.x < 16) atomicAdd(&g_sumsq[threadIdx.x], red[threadIdx.x]);
}

// -------- K2: inverse norm (16 values) --------
__global__ void k_norm()
{
    int t = threadIdx.x;
    if (t < 16) g_inv[t] = 1.f / fmaxf(sqrtf(g_sumsq[t]), 1e-12f);
}

// -------- K_node: per-node precompute qn = h@Wq + bq, hkv = h@Wkv[16:80] --------
// 128 nodes/block, 256 threads; thread (ng,og): ng=tid>>4 owns 8 node rows,
// og owns q cols og*4..+3 and hkv cols og*8..+7.
__global__ __launch_bounds__(256, 2) void k_node(
    const float* __restrict__ h,
    const float* __restrict__ Wq, const float* __restrict__ bq,
    const float* __restrict__ Wkv)
{
    extern __shared__ float smn[];
    float* sW = smn;            // 12288 floats: Wq (4096) | Wkv_mid (8192)
    float* sH = smn + 12288;    // 128*LDH = 8704

    const int tid = threadIdx.x;
    const int n0 = blockIdx.x * 128;

    for (int i = tid; i < 1024; i += 256)
        ((float4*)sW)[i] = ((const float4*)Wq)[i];
    for (int i = tid; i < 2048; i += 256)
        ((float4*)(sW + 4096))[i] = ((const float4*)(Wkv + 16 * 128))[i];
    for (int idx = tid; idx < 128 * 16; idx += 256) {
        int n = idx >> 4, c4 = idx & 15;
        float4 v = make_float4(0.f, 0.f, 0.f, 0.f);
        if (n0 + n < N_NODES)
            v = *(const float4*)(h + (size_t)(n0 + n) * 64 + c4 * 4);
        *(float4*)(sH + n * LDH + c4 * 4) = v;
    }
    __syncthreads();

    const int ng = tid >> 4, og = tid & 15;
    const float* hBase = sH + ng * 8 * LDH;

    // ---- q pass ----
    float accq[8][4];
    {
        float4 b = *(const float4*)(bq + og * 4);
#pragma unroll
        for (int i = 0; i < 8; i++) { accq[i][0]=b.x; accq[i][1]=b.y; accq[i][2]=b.z; accq[i][3]=b.w; }
    }
#pragma unroll 2
    for (int k4 = 0; k4 < 16; k4++) {
        float4 a4[8];
#pragma unroll
        for (int i = 0; i < 8; i++)
            a4[i] = *(const float4*)(hBase + i * LDH + k4 * 4);
#pragma unroll
        for (int kk = 0; kk < 4; kk++) {
            float4 w = *(const float4*)(sW + (k4 * 4 + kk) * 64 + og * 4);
#pragma unroll
            for (int i = 0; i < 8; i++) {
                float a = ((const float*)&a4[i])[kk];
                accq[i][0] += a * w.x; accq[i][1] += a * w.y;
                accq[i][2] += a * w.z; accq[i][3] += a * w.w;
            }
        }
    }
#pragma unroll
    for (int i = 0; i < 8; i++) {
        int n = n0 + ng * 8 + i;
        if (n < N_NODES)
            *(float4*)(g_qn + (size_t)n * 64 + og * 4) =
                make_float4(accq[i][0], accq[i][1], accq[i][2], accq[i][3]);
    }

    // ---- hkv pass (h @ Wkv_mid, no bias) ----
    float acc[8][8];
#pragma unroll
    for (int i = 0; i < 8; i++)
#pragma unroll
        for (int c = 0; c < 8; c++) acc[i][c] = 0.f;
#pragma unroll 2
    for (int k4 = 0; k4 < 16; k4++) {
#pragma unroll
        for (int half = 0; half < 2; half++) {
            float4 a4[4];
#pragma unroll
            for (int i = 0; i < 4; i++)
                a4[i] = *(const float4*)(hBase + (half * 4 + i) * LDH + k4 * 4);
#pragma unroll
            for (int kk = 0; kk < 4; kk++) {
                const float* wp = sW + 4096 + (k4 * 4 + kk) * 128 + og * 8;
                float4 w0 = *(const float4*)wp;
                float4 w1 = *(const float4*)(wp + 4);
#pragma unroll
                for (int i = 0; i < 4; i++) {
                    float a = ((const float*)&a4[i])[kk];
                    int ii = half * 4 + i;
                    acc[ii][0] += a * w0.x; acc[ii][1] += a * w0.y;
                    acc[ii][2] += a * w0.z; acc[ii][3] += a * w0.w;
                    acc[ii][4] += a * w1.x; acc[ii][5] += a * w1.y;
                    acc[ii][6] += a * w1.z; acc[ii][7] += a * w1.w;
                }
            }
        }
    }
#pragma unroll
    for (int i = 0; i < 8; i++) {
        int n = n0 + ng * 8 + i;
        if (n < N_NODES) {
            float* dst = g_hkv + (size_t)n * 128 + og * 8;
            *(float4*)dst = make_float4(acc[i][0], acc[i][1], acc[i][2], acc[i][3]);
            *(float4*)(dst + 4) = make_float4(acc[i][4], acc[i][5], acc[i][6], acc[i][7]);
        }
    }
}

// -------- K3: fused edge kernel (per-edge part only) --------
// kv = bkv + hkv[col] + [radial' | edge_attr] @ Wkv'[32 rows];
// alpha = qn[row]·k; exp; MLP silu(v@W1+b1)@W2; scatter unnormalized numerators.
__global__ __launch_bounds__(256, 2) void k_fused(
    const float* __restrict__ edge_attr,
    const int* __restrict__ row, const int* __restrict__ col,
    const float* __restrict__ Wkv, const float* __restrict__ bkv,
    const float* __restrict__ W1, const float* __restrict__ b1,
    const float* __restrict__ W2,
    float* __restrict__ ex_out)
{
    extern __shared__ float sm[];
    float* sW  = sm;                 // 4416: Wkv' 32x128 (4096) | later W1(4096)+W2(256)+b1(64)
    float* sA  = sm + 4416;          // 8704: feat TE x LDF, then v TE x LDV
    float* sEx = sm + 13120;         // 128
    float* sU  = sm + 13248;         // 512
    int* sRow  = (int*)(sm + 13760); // 128
    int* sCol  = sRow + TE;          // 128

    const int tid = threadIdx.x;
    const int e0 = blockIdx.x * TE;

    if (tid < TE) sRow[tid] = row[e0 + tid];
    else sCol[tid - TE] = col[e0 + tid - TE];

    // stage Wkv' : rows 0..15 and 80..95 of Wkv -> 32 x 128
    for (int i = tid; i < 1024; i += 256) {
        int r = i >> 5, q = i & 31;
        int srcr = (r < 16) ? r : (r + 64);
        ((float4*)sW)[i] = *(const float4*)(Wkv + srcr * 128 + q * 4);
    }
    // stage feat = [radial*inv (16) | edge_attr (16)]
    for (int idx = tid; idx < TE * 8; idx += 256) {
        int e = idx >> 3, c4 = idx & 7;
        float4 v;
        if (c4 < 4) {
            v = *(const float4*)(g_radial + (size_t)(e0 + e) * 16 + c4 * 4);
            float4 inv = *(const float4*)(g_inv + c4 * 4);
            v.x *= inv.x; v.y *= inv.y; v.z *= inv.z; v.w *= inv.w;
        } else {
            v = *(const float4*)(edge_attr + (size_t)(e0 + e) * 16 + (c4 - 4) * 4);
        }
        *(float4*)(sA + e * LDF + c4 * 4) = v;
    }
    __syncthreads();

    const int eg = tid >> 4, og = tid & 15;
    const float* aBase = sA + eg * 8 * LDF;

    // ---- acc init: bkv + gathered hkv[col] ----
    float acc[8][8];
    {
        float4 b0 = *(const float4*)(bkv + og * 8);
        float4 b1v = *(const float4*)(bkv + og * 8 + 4);
#pragma unroll
        for (int i = 0; i < 8; i++) {
            const float* hp = g_hkv + (size_t)sCol[eg * 8 + i] * 128 + og * 8;
            float4 h0 = *(const float4*)hp;
            float4 h1 = *(const float4*)(hp + 4);
            acc[i][0]=b0.x+h0.x; acc[i][1]=b0.y+h0.y; acc[i][2]=b0.z+h0.z; acc[i][3]=b0.w+h0.w;
            acc[i][4]=b1v.x+h1.x; acc[i][5]=b1v.y+h1.y; acc[i][6]=b1v.z+h1.z; acc[i][7]=b1v.w+h1.w;
        }
    }

    // ---- per-edge GEMM: 32 k-steps ----
#pragma unroll
    for (int k4 = 0; k4 < 8; k4++) {
#pragma unroll
        for (int half = 0; half < 2; half++) {
            float4 a4[4];
#pragma unroll
            for (int i = 0; i < 4; i++)
                a4[i] = *(const float4*)(aBase + (half * 4 + i) * LDF + k4 * 4);
#pragma unroll
            for (int kk = 0; kk < 4; kk++) {
                const float* wp = sW + (k4 * 4 + kk) * 128 + og * 8;
                float4 w0 = *(const float4*)wp;
                float4 w1 = *(const float4*)(wp + 4);
#pragma unroll
                for (int i = 0; i < 4; i++) {
                    float a = ((const float*)&a4[i])[kk];
                    int ii = half * 4 + i;
                    acc[ii][0] += a * w0.x; acc[ii][1] += a * w0.y;
                    acc[ii][2] += a * w0.z; acc[ii][3] += a * w0.w;
                    acc[ii][4] += a * w1.x; acc[ii][5] += a * w1.y;
                    acc[ii][6] += a * w1.z; acc[ii][7] += a * w1.w;
                }
            }
        }
    }

    // ---- alpha = qn[row]·k (even cols) ----
    float p[8];
#pragma unroll
    for (int i = 0; i < 8; i++) {
        float4 q4 = *(const float4*)(g_qn + (size_t)sRow[eg * 8 + i] * 64 + og * 4);
        p[i] = q4.x*acc[i][0] + q4.y*acc[i][2] + q4.z*acc[i][4] + q4.w*acc[i][6];
    }
#pragma unroll
    for (int off = 8; off > 0; off >>= 1)
#pragma unroll
        for (int i = 0; i < 8; i++)
            p[i] += __shfl_down_sync(0xffffffffu, p[i], off, 16);

    if (og == 0) {
#pragma unroll
        for (int i = 0; i < 8; i++) {
            int el = eg * 8 + i;
            float ex = __expf(p[i]);     // softmax shift-invariant; |alpha| <~ 15
            sEx[el] = ex;
            ex_out[e0 + el] = ex;        // normalized in k_final
            atomicAdd(&g_segsum[sRow[el]], ex);
        }
    }
    __syncthreads();   // feat + Wkv' reads done; sEx visible after next sync

    // ---- write v (odd cols) to sA as TE x LDV tile; stage W1/W2/b1 ----
#pragma unroll
    for (int i = 0; i < 8; i++)
        *(float4*)(sA + (eg * 8 + i) * LDV + og * 4) =
            make_float4(acc[i][1], acc[i][3], acc[i][5], acc[i][7]);

    for (int i = tid; i < 1024; i += 256)
        ((float4*)sW)[i] = ((const float4*)W1)[i];
    if (tid < 64) ((float4*)(sW + 4096))[tid] = ((const float4*)W2)[tid];
    else if (tid < 80) ((float4*)(sW + 4352))[tid - 64] = ((const float4*)b1)[tid - 64];
    __syncthreads();

    // ---- t = silu(v @ W1 + b1) ----
    const float* vBase = sA + eg * 8 * LDV;
    float acct[8][4];
    {
        float4 b = *(const float4*)(sW + 4352 + og * 4);
#pragma unroll
        for (int i = 0; i < 8; i++) { acct[i][0]=b.x; acct[i][1]=b.y; acct[i][2]=b.z; acct[i][3]=b.w; }
    }
#pragma unroll 2
    for (int k4 = 0; k4 < 16; k4++) {
        float4 a4[8];
#pragma unroll
        for (int i = 0; i < 8; i++)
            a4[i] = *(const float4*)(vBase + i * LDV + k4 * 4);
#pragma unroll
        for (int kk = 0; kk < 4; kk++) {
            float4 w = *(const float4*)(sW + (k4 * 4 + kk) * 64 + og * 4);
#pragma unroll
            for (int i = 0; i < 8; i++) {
                float a = ((const float*)&a4[i])[kk];
                acct[i][0] += a * w.x; acct[i][1] += a * w.y;
                acct[i][2] += a * w.z; acct[i][3] += a * w.w;
            }
        }
    }
#pragma unroll
    for (int i = 0; i < 8; i++)
#pragma unroll
        for (int c = 0; c < 4; c++) {
            float x = acct[i][c];
            acct[i][c] = x / (1.f + __expf(-x));
        }

    // ---- u = t @ W2 (reduce across og) ----
    float pu[8][4];
#pragma unroll
    for (int i = 0; i < 8; i++) { pu[i][0]=0.f; pu[i][1]=0.f; pu[i][2]=0.f; pu[i][3]=0.f; }
#pragma unroll
    for (int c = 0; c < 4; c++) {
        float4 w2 = *(const float4*)(sW + 4096 + (og * 4 + c) * 4);
#pragma unroll
        for (int i = 0; i < 8; i++) {
            float t = acct[i][c];
            pu[i][0] += t * w2.x; pu[i][1] += t * w2.y;
            pu[i][2] += t * w2.z; pu[i][3] += t * w2.w;
        }
    }
#pragma unroll
    for (int off = 8; off > 0; off >>= 1)
#pragma unroll
        for (int i = 0; i < 8; i++)
#pragma unroll
            for (int c2 = 0; c2 < 4; c2++)
                pu[i][c2] += __shfl_down_sync(0xffffffffu, pu[i][c2], off, 16);
    if (og == 0) {
#pragma unroll
        for (int i = 0; i < 8; i++)
            *(float4*)(sU + (eg * 8 + i) * 4) = make_float4(pu[i][0], pu[i][1], pu[i][2], pu[i][3]);
    }
    __syncthreads();

    // ---- scatter unnormalized numerators (16B vector atomics) ----
    for (int idx = tid; idx < TE * 16; idx += 256) {
        int e = idx >> 4, c4 = idx & 15;
        float ex = sEx[e];
        float4 v4 = *(const float4*)(sA + e * LDV + c4 * 4);
        red_add_v4(g_hnum + (size_t)sRow[e] * 64 + c4 * 4,
                   ex * v4.x, ex * v4.y, ex * v4.z, ex * v4.w);
    }
    for (int idx = tid; idx < TE * 3; idx += 256) {
        int e = idx / 3, pp = idx % 3;
        float ex = sEx[e];
        const float* dp = g_diff + (size_t)(e0 + e) * 12 + pp * 4;
        float vals[4];
#pragma unroll
        for (int j = 0; j < 4; j++) {
            int jj = pp * 4 + j;
            int ch = jj / 3;
            vals[j] = dp[j] * (ex * sU[e * 4 + ch]);
        }
        red_add_v4(g_cnum + (size_t)sRow[e] * 12 + pp * 4,
                   vals[0], vals[1], vals[2], vals[3]);
    }
}

// -------- K4: normalize everything into out --------
__global__ void k_final(const float* __restrict__ h, const float* __restrict__ coord,
                        const int* __restrict__ row, float* __restrict__ out)
{
    int i = blockIdx.x * 256 + threadIdx.x;
    if (i < 3200000) {
        out[i] = h[i] + g_hnum[i] / g_segsum[i >> 6];
    } else if (i < 3800000) {
        int j = i - 3200000;
        out[i] = coord[j] + g_cnum[j] / g_segsum[j / 12];
    } else if (i < 4600000) {
        int e = i - 3800000;
        out[i] = out[i] / g_segsum[row[e]];
    }
}

// -------- launch --------
extern "C" void kernel_launch(void* const* d_in, const int* in_sizes, int n_in,
                              void* d_out, int out_size)
{
    const float *h=0, *coord=0, *edge_attr=0, *Wq=0, *bq=0, *Wkv=0, *bkv=0, *W1=0, *b1=0, *W2=0;
    const int *row=0, *col=0;
    for (int i = 0; i < n_in; i++) {
        int s = in_sizes[i]; const void* p = d_in[i];
        switch (s) {
            case 3200000:  h = (const float*)p; break;
            case 600000:   coord = (const float*)p; break;
            case 800000:   if (!row) row = (const int*)p; else col = (const int*)p; break;
            case 12800000: edge_attr = (const float*)p; break;
            case 4096:     if (!Wq) Wq = (const float*)p; else W1 = (const float*)p; break;
            case 64:       if (!bq) bq = (const float*)p; else b1 = (const float*)p; break;
            case 12288:    Wkv = (const float*)p; break;
            case 128:      bkv = (const float*)p; break;
            case 256:      W2 = (const float*)p; break;
            default: break;
        }
    }
    float* out = (float*)d_out;
    float* att = out + 3800000;

    cudaFuncSetAttribute(k_node,  cudaFuncAttributeMaxDynamicSharedMemorySize, 84992);
    cudaFuncSetAttribute(k_fused, cudaFuncAttributeMaxDynamicSharedMemorySize, 57344);

    k_init<<<(3850016 + 255) / 256, 256>>>();
    k_radial<<<N_EDGES / 256, 256>>>(coord, row, col);
    k_norm<<<1, 16>>>();
    k_node<<<(N_NODES + 127) / 128, 256, 84992>>>(h, Wq, bq, Wkv);
    k_fused<<<N_EDGES / TE, 256, 57344>>>(edge_attr, row, col,
                                          Wkv, bkv, W1, b1, W2, att);
    k_final<<<(4600000 + 255) / 256, 256>>>(h, coord, row, out);
}